// round 4
// baseline (speedup 1.0000x reference)
#include <cuda_runtime.h>
#include <cuda_bf16.h>
#include <math.h>
#include <stdint.h>

#define TSTEPS 5
#define BATCH  128
#define IN0    512
#define HID    1024
#define G4     4096
#define OUTD   32

// bulk GEMM tiles (XG kernels)
#define BM 128
#define BN 128
#define BK 32
#define NTH 256
#define RS 40            // smem row stride (bf16) for bulk GEMM

// persistent recurrence kernel
#define PU   8           // hidden units per CTA
#define NCTA 128         // 1024/8
#define RSW  1032        // W smem row stride (bf16 elems), 1024 + 8 pad
#define RSA  40          // A chunk row stride
#define PK   32          // k chunk
#define SW_BYTES   (2 * 32 * RSW * 2)                 // 132096
#define SA_BYTES   (2 * 2 * 128 * RSA * 2)            // 40960
#define PERSIST_SMEM (SW_BYTES + SA_BYTES)            // 173056

// Scratch (device globals; no allocations allowed)
__device__ float g_xg0 [TSTEPS * BATCH * G4];
__device__ float g_xg1 [TSTEPS * BATCH * G4];
__device__ float g_h1  [TSTEPS * BATCH * HID];
__device__ float g_h2  [TSTEPS * BATCH * HID];
__device__ int   g_ctr [2][4];
__device__ int   g_pass[2];

__device__ __forceinline__ uint32_t smem_u32(const void* p) {
    uint32_t a;
    asm("{ .reg .u64 t; cvta.to.shared.u64 t, %1; cvt.u32.u64 %0, t; }"
        : "=r"(a) : "l"(p));
    return a;
}

#define LDSM_X4(R, addr)                                                     \
    asm volatile("ldmatrix.sync.aligned.m8n8.x4.shared.b16 "                 \
                 "{%0,%1,%2,%3}, [%4];"                                      \
                 : "=r"((R)[0]), "=r"((R)[1]), "=r"((R)[2]), "=r"((R)[3])    \
                 : "r"(addr))
#define LDSM_X2(R, addr)                                                     \
    asm volatile("ldmatrix.sync.aligned.m8n8.x2.shared.b16 {%0,%1}, [%2];"   \
                 : "=r"((R)[0]), "=r"((R)[1]) : "r"(addr))
#define MMA_BF16(D, Ar, Br)                                                  \
    asm volatile("mma.sync.aligned.m16n8k16.row.col.f32.bf16.bf16.f32 "      \
                 "{%0,%1,%2,%3}, {%4,%5,%6,%7}, {%8,%9}, {%0,%1,%2,%3};"     \
                 : "+f"((D)[0]), "+f"((D)[1]), "+f"((D)[2]), "+f"((D)[3])    \
                 : "r"((Ar)[0]), "r"((Ar)[1]), "r"((Ar)[2]), "r"((Ar)[3]),   \
                   "r"((Br)[0]), "r"((Br)[1]))

__device__ __forceinline__ void split_bf16(float f, uint16_t& h, uint16_t& l) {
    __nv_bfloat16 hb = __float2bfloat16(f);
    __nv_bfloat16 lb = __float2bfloat16(f - __bfloat162float(hb));
    h = __bfloat16_as_ushort(hb);
    l = __bfloat16_as_ushort(lb);
}
__device__ __forceinline__ float sigf(float x) { return 1.f / (1.f + expf(-x)); }

// ---------------------------------------------------------------------------
// Bulk tensor-core GEMM (XG precompute): C = A[M,K] @ W[N,K]^T + b1 + b2
// ---------------------------------------------------------------------------
__global__ __launch_bounds__(NTH) void hmma_gemm(
    const float* __restrict__ A, const float* __restrict__ W,
    int strideA, int strideW, int ksize,
    const float* __restrict__ b1, const float* __restrict__ b2,
    float* __restrict__ C, int ldc)
{
    __shared__ uint16_t sA[2][BM * RS];
    __shared__ uint16_t sW[2][BN * RS];

    const int tid  = threadIdx.x;
    const int lane = tid & 31;
    const int warp = tid >> 5;
    const int wm   = warp >> 2;
    const int wn   = warp & 3;
    const int row0 = blockIdx.y * BM;
    const int col0 = blockIdx.x * BN;
    const int nch  = ksize / BK;

    const bool isA = (tid < 128);
    const int  t2  = tid & 127;
    const float* src = isA ? (A + (size_t)row0 * strideA)
                           : (W + (size_t)col0 * strideW);
    const int sstr = isA ? strideA : strideW;
    uint16_t* d0 = isA ? sA[0] : sW[0];
    uint16_t* d1 = isA ? sA[1] : sW[1];

    float4 pf[8];
    const uint32_t bA0 = smem_u32(sA[0]);
    const uint32_t bA1 = smem_u32(sA[1]);
    const uint32_t bW0 = smem_u32(sW[0]);
    const uint32_t bW1 = smem_u32(sW[1]);

    float acc[4][4][4];
#pragma unroll
    for (int i = 0; i < 4; i++)
#pragma unroll
        for (int j = 0; j < 4; j++)
#pragma unroll
            for (int v = 0; v < 4; v++) acc[i][j][v] = 0.f;

#pragma unroll
    for (int i = 0; i < 8; i++) {
        int idx = t2 + 128 * i;
        int r = idx >> 3, c4 = idx & 7;
        pf[i] = *(const float4*)(src + (size_t)r * sstr + c4 * 4);
    }

    const int rl  = lane & 7;
    const int s8  = (lane >> 3) & 1;
    const int s16 = (lane >> 4) & 1;

    for (int c = 0; c < nch; c++) {
#pragma unroll
        for (int i = 0; i < 8; i++) {
            int idx = t2 + 128 * i;
            int r = idx >> 3, c4 = idx & 7;
            float f[4] = {pf[i].x, pf[i].y, pf[i].z, pf[i].w};
            uint16_t h[4], l[4];
#pragma unroll
            for (int j = 0; j < 4; j++) split_bf16(f[j], h[j], l[j]);
            int o = r * RS + c4 * 4;
            *(uint2*)(d0 + o) = *(uint2*)h;
            *(uint2*)(d1 + o) = *(uint2*)l;
        }
        __syncthreads();

        if (c + 1 < nch) {
            const int kk = (c + 1) * BK;
#pragma unroll
            for (int i = 0; i < 8; i++) {
                int idx = t2 + 128 * i;
                int r = idx >> 3, c4 = idx & 7;
                pf[i] = *(const float4*)(src + (size_t)r * sstr + kk + c4 * 4);
            }
        }

#pragma unroll
        for (int ks = 0; ks < 2; ks++) {
            const int k0b = (ks * 16 + s8 * 8) * 2;
            const int k0a = (ks * 16 + s16 * 8) * 2;
            uint32_t bh[4][2], bl[4][2];
#pragma unroll
            for (int nt = 0; nt < 4; nt++) {
                uint32_t ro = (uint32_t)(wn * 32 + nt * 8 + rl) * (RS * 2) + k0b;
                LDSM_X2(bh[nt], bW0 + ro);
                LDSM_X2(bl[nt], bW1 + ro);
            }
#pragma unroll
            for (int mt = 0; mt < 4; mt++) {
                uint32_t ro = (uint32_t)(wm * 64 + mt * 16 + rl + s8 * 8) * (RS * 2) + k0a;
                uint32_t ah[4], al[4];
                LDSM_X4(ah, bA0 + ro);
                LDSM_X4(al, bA1 + ro);
#pragma unroll
                for (int nt = 0; nt < 4; nt++) {
                    MMA_BF16(acc[mt][nt], ah, bh[nt]);
                    MMA_BF16(acc[mt][nt], ah, bl[nt]);
                    MMA_BF16(acc[mt][nt], al, bh[nt]);
                }
            }
        }
        __syncthreads();
    }

#pragma unroll
    for (int mt = 0; mt < 4; mt++) {
        int row = row0 + wm * 64 + mt * 16 + (lane >> 2);
#pragma unroll
        for (int nt = 0; nt < 4; nt++) {
            int col = col0 + wn * 32 + nt * 8 + (lane & 3) * 2;
            float bb0 = b1[col] + b2[col];
            float bb1 = b1[col + 1] + b2[col + 1];
            float2 v0 = make_float2(acc[mt][nt][0] + bb0, acc[mt][nt][1] + bb1);
            float2 v1 = make_float2(acc[mt][nt][2] + bb0, acc[mt][nt][3] + bb1);
            *(float2*)(C + (size_t)row * ldc + col) = v0;
            *(float2*)(C + (size_t)(row + 8) * ldc + col) = v1;
        }
    }
}

// ---------------------------------------------------------------------------
// Persistent fused LSTM recurrence (one layer, 5 steps, NCTA=128 CTAs).
// CTA bid owns hidden units j0..j0+7 for ALL gates: local cols = gate*8 + u.
// c-state lives in registers; h round-trips via gmem (.cg) with a grid barrier.
// ---------------------------------------------------------------------------
__global__ __launch_bounds__(256) void lstm_persist(
    const float* __restrict__ Whh,   // [G4][HID]
    const float* __restrict__ xg,    // [TSTEPS][BATCH][G4]
    float* __restrict__ hseq,        // [TSTEPS][BATCH][HID]
    int layer)
{
    extern __shared__ char smem[];
    const int tid  = threadIdx.x;
    const int lane = tid & 31;
    const int warp = tid >> 5;
    const int j0   = blockIdx.x * PU;

    const uint32_t sb  = smem_u32(smem);
    const uint32_t bW0 = sb;
    const uint32_t bW1 = sb + 32 * RSW * 2;
    // A chunk buffers: byte offset SW_BYTES + (buf*2+comp)*128*RSA*2
    char* aBase = smem + SW_BYTES;

    // ---- Preload W slice (32 gathered rows x 1024) as bf16 hi/lo ----
    {
        uint16_t* w0 = (uint16_t*)smem;
        uint16_t* w1 = w0 + 32 * RSW;
#pragma unroll
        for (int i = 0; i < 32; i++) {
            int idx = tid + 256 * i;        // 0..8191 float4 slots
            int r   = idx >> 8;             // local row 0..31
            int c4  = (idx & 255) * 4;      // col
            int grow = (r >> 3) * HID + j0 + (r & 7);   // gate*1024 + j0+u
            float4 f = *(const float4*)(Whh + (size_t)grow * HID + c4);
            float fv[4] = {f.x, f.y, f.z, f.w};
            uint16_t h[4], l[4];
#pragma unroll
            for (int j = 0; j < 4; j++) split_bf16(fv[j], h[j], l[j]);
            *(uint2*)(w0 + r * RSW + c4) = *(uint2*)h;
            *(uint2*)(w1 + r * RSW + c4) = *(uint2*)l;
        }
    }
    __syncthreads();

    // Epilogue/fragment mapping
    const int rl  = lane & 7;
    const int s8  = (lane >> 3) & 1;
    const int s16 = (lane >> 4) & 1;
    const int b0  = warp * 16 + (lane >> 2);   // batch row (and +8)
    const int u0  = (lane & 3) * 2;            // unit pair

    float cst[4] = {0.f, 0.f, 0.f, 0.f};       // c[(rh,up)] persists in regs

    // ---- t = 0: gates from xg only ----
    {
        const float* xgt = xg;
        float* ht = hseq;
#pragma unroll
        for (int rh = 0; rh < 2; rh++) {
            int rr = b0 + rh * 8;
            float2 xi = *(const float2*)(xgt + (size_t)rr * G4 + 0 * HID + j0 + u0);
            float2 xf = *(const float2*)(xgt + (size_t)rr * G4 + 1 * HID + j0 + u0);
            float2 xc = *(const float2*)(xgt + (size_t)rr * G4 + 2 * HID + j0 + u0);
            float2 xo = *(const float2*)(xgt + (size_t)rr * G4 + 3 * HID + j0 + u0);
            float hv[2];
#pragma unroll
            for (int up = 0; up < 2; up++) {
                float gi = up ? xi.y : xi.x, gf = up ? xf.y : xf.x;
                float gc = up ? xc.y : xc.x, go = up ? xo.y : xo.x;
                int ci = rh * 2 + up;
                cst[ci] = sigf(gf) * cst[ci] + sigf(gi) * tanhf(gc);
                hv[up]  = sigf(go) * tanhf(cst[ci]);
            }
            __stcg((float2*)(ht + (size_t)rr * HID + j0 + u0),
                   make_float2(hv[0], hv[1]));
        }
    }

    // ---- grid barrier helper (inlined) + steps 1..4 ----
    for (int t = 1; t < TSTEPS; t++) {
        // barrier: h[t-1] complete chip-wide
        __threadfence();
        __syncthreads();
        if (tid == 0) {
            atomicAdd(&g_ctr[layer][t - 1], 1);
            while (atomicAdd(&g_ctr[layer][t - 1], 0) < NCTA) __nanosleep(64);
        }
        __syncthreads();

        const float* hprev = hseq + (size_t)(t - 1) * BATCH * HID;

        float acc[4][4];
#pragma unroll
        for (int i = 0; i < 4; i++)
#pragma unroll
            for (int j = 0; j < 4; j++) acc[i][j] = 0.f;

        // prefetch chunk 0: row = tid/2, k-base = (tid&1)*16
        const int ar = tid >> 1;
        const int ak = (tid & 1) * 16;
        float4 pf[4];
#pragma unroll
        for (int i = 0; i < 4; i++)
            pf[i] = __ldcg((const float4*)(hprev + (size_t)ar * HID + ak + i * 4));

        for (int c = 0; c < HID / PK; c++) {
            const int buf = c & 1;
            char* ab = aBase + buf * (2 * 128 * RSA * 2);
            uint16_t* a0 = (uint16_t*)ab;
            uint16_t* a1 = a0 + 128 * RSA;
#pragma unroll
            for (int i = 0; i < 4; i++) {
                float fv[4] = {pf[i].x, pf[i].y, pf[i].z, pf[i].w};
                uint16_t h[4], l[4];
#pragma unroll
                for (int j = 0; j < 4; j++) split_bf16(fv[j], h[j], l[j]);
                int o = ar * RSA + ak + i * 4;
                *(uint2*)(a0 + o) = *(uint2*)h;
                *(uint2*)(a1 + o) = *(uint2*)l;
            }
            __syncthreads();

            if (c + 1 < HID / PK) {
                const int kk = (c + 1) * PK + ak;
#pragma unroll
                for (int i = 0; i < 4; i++)
                    pf[i] = __ldcg((const float4*)(hprev + (size_t)ar * HID + kk + i * 4));
            }

            const uint32_t aB0 = sb + SW_BYTES + buf * (2 * 128 * RSA * 2);
            const uint32_t aB1 = aB0 + 128 * RSA * 2;
#pragma unroll
            for (int ks = 0; ks < 2; ks++) {
                const int kw = (c * PK + ks * 16 + s8 * 8) * 2;   // W smem byte col
                const int ka = (ks * 16 + s16 * 8) * 2;           // A smem byte col
                uint32_t bh[4][2], bl[4][2];
#pragma unroll
                for (int nt = 0; nt < 4; nt++) {
                    uint32_t ro = (uint32_t)(nt * 8 + rl) * (RSW * 2) + kw;
                    LDSM_X2(bh[nt], bW0 + ro);
                    LDSM_X2(bl[nt], bW1 + ro);
                }
                uint32_t ro = (uint32_t)(warp * 16 + rl + s8 * 8) * (RSA * 2) + ka;
                uint32_t ah[4], al[4];
                LDSM_X4(ah, aB0 + ro);
                LDSM_X4(al, aB1 + ro);
#pragma unroll
                for (int nt = 0; nt < 4; nt++) {
                    MMA_BF16(acc[nt], ah, bh[nt]);
                    MMA_BF16(acc[nt], ah, bl[nt]);
                    MMA_BF16(acc[nt], al, bh[nt]);
                }
            }
            __syncthreads();
        }

        // epilogue: gates
        const float* xgt = xg + (size_t)t * BATCH * G4;
        float* ht = hseq + (size_t)t * BATCH * HID;
#pragma unroll
        for (int rh = 0; rh < 2; rh++) {
            int rr = b0 + rh * 8;
            float2 xi = *(const float2*)(xgt + (size_t)rr * G4 + 0 * HID + j0 + u0);
            float2 xf = *(const float2*)(xgt + (size_t)rr * G4 + 1 * HID + j0 + u0);
            float2 xc = *(const float2*)(xgt + (size_t)rr * G4 + 2 * HID + j0 + u0);
            float2 xo = *(const float2*)(xgt + (size_t)rr * G4 + 3 * HID + j0 + u0);
            float hv[2];
#pragma unroll
            for (int up = 0; up < 2; up++) {
                float gi = (up ? xi.y : xi.x) + acc[0][rh * 2 + up];
                float gf = (up ? xf.y : xf.x) + acc[1][rh * 2 + up];
                float gc = (up ? xc.y : xc.x) + acc[2][rh * 2 + up];
                float go = (up ? xo.y : xo.x) + acc[3][rh * 2 + up];
                int ci = rh * 2 + up;
                cst[ci] = sigf(gf) * cst[ci] + sigf(gi) * tanhf(gc);
                hv[up]  = sigf(go) * tanhf(cst[ci]);
            }
            __stcg((float2*)(ht + (size_t)rr * HID + j0 + u0),
                   make_float2(hv[0], hv[1]));
        }
    }

    // ---- exit protocol: reset counters deterministically ----
    __threadfence();
    __syncthreads();
    if (tid == 0) {
        atomicAdd(&g_pass[layer], 1);
        if (blockIdx.x == 0) {
            while (atomicAdd(&g_pass[layer], 0) < NCTA) __nanosleep(64);
#pragma unroll
            for (int b = 0; b < 4; b++) atomicExch(&g_ctr[layer][b], 0);
            atomicExch(&g_pass[layer], 0);
        }
    }
}

// ---------------------------------------------------------------------------
// Head: out[b,o] = dot(h2[4][b,:], Wout[o,:]) + bout[o]
// ---------------------------------------------------------------------------
__global__ __launch_bounds__(256) void head_kernel(
    const float* __restrict__ hfin,
    const float* __restrict__ Wout, const float* __restrict__ bout,
    float* __restrict__ out)
{
    __shared__ float hs[HID];
    __shared__ float red[8][32];
    int b = blockIdx.x;
    for (int i = threadIdx.x; i < HID; i += 256) hs[i] = hfin[(size_t)b * HID + i];
    __syncthreads();

    int o     = threadIdx.x % 32;
    int chunk = threadIdx.x / 32;
    float s = 0.f;
    const float* wrow = Wout + (size_t)o * HID;
#pragma unroll 4
    for (int k = chunk * 128; k < chunk * 128 + 128; k++)
        s = fmaf(hs[k], wrow[k], s);
    red[chunk][o] = s;
    __syncthreads();

    if (threadIdx.x < 32) {
        float t = 0.f;
#pragma unroll
        for (int ch = 0; ch < 8; ch++) t += red[ch][threadIdx.x];
        out[(size_t)b * OUTD + threadIdx.x] = t + bout[threadIdx.x];
    }
}

// ---------------------------------------------------------------------------
// Host launcher (5 kernel launches total)
// ---------------------------------------------------------------------------
extern "C" void kernel_launch(void* const* d_in, const int* in_sizes, int n_in,
                              void* d_out, int out_size)
{
    const float* input = (const float*)d_in[0];
    const float* w_ih0 = (const float*)d_in[1];
    const float* w_hh0 = (const float*)d_in[2];
    const float* b_ih0 = (const float*)d_in[3];
    const float* b_hh0 = (const float*)d_in[4];
    const float* w_ih1 = (const float*)d_in[5];
    const float* w_hh1 = (const float*)d_in[6];
    const float* b_ih1 = (const float*)d_in[7];
    const float* b_hh1 = (const float*)d_in[8];
    const float* w_out = (const float*)d_in[9];
    const float* b_out = (const float*)d_in[10];
    float* out = (float*)d_out;

    cudaFuncSetAttribute(lstm_persist,
                         cudaFuncAttributeMaxDynamicSharedMemorySize,
                         PERSIST_SMEM);

    float *xg0, *xg1, *h1, *h2;
    cudaGetSymbolAddress((void**)&xg0, g_xg0);
    cudaGetSymbolAddress((void**)&xg1, g_xg1);
    cudaGetSymbolAddress((void**)&h1,  g_h1);
    cudaGetSymbolAddress((void**)&h2,  g_h2);

    // 1) XG0 = input[0:640] @ w_ih0^T + biases   [640, 4096]
    {
        dim3 grid(G4 / BN, TSTEPS * BATCH / BM);
        hmma_gemm<<<grid, NTH>>>(input, w_ih0, IN0, IN0, IN0,
                                 b_ih0, b_hh0, xg0, G4);
    }
    // 2) Layer-0 fused recurrence (writes h1[0..4])
    lstm_persist<<<NCTA, 256, PERSIST_SMEM>>>(w_hh0, xg0, h1, 0);

    // 3) XG1 = h1 @ w_ih1^T + biases   [640, 4096]
    {
        dim3 grid(G4 / BN, TSTEPS * BATCH / BM);
        hmma_gemm<<<grid, NTH>>>(h1, w_ih1, HID, HID, HID,
                                 b_ih1, b_hh1, xg1, G4);
    }
    // 4) Layer-1 fused recurrence (writes h2[0..4])
    lstm_persist<<<NCTA, 256, PERSIST_SMEM>>>(w_hh1, xg1, h2, 1);

    // 5) Linear head on h2[4]
    head_kernel<<<BATCH, 256>>>(h2 + (size_t)4 * BATCH * HID, w_out, b_out, out);
}